// round 16
// baseline (speedup 1.0000x reference)
#include <cuda_runtime.h>
#include <math.h>
#include <stdint.h>

#define G_   4
#define HW   4096
#define N_   32
#define TH   16
#define TW   16
#define HALO 3
#define SH   22
#define SW   22
#define THREADS 128
#define PPT  2

// smem layout (bytes). Stage (SoA, 8KB) aliases conv-weight table (11.5KB):
// Phase A reads swc, Phase B writes stage; __syncthreads between.
#define OFF_STAGE 0
#define SWC_U64   1440                      // [pos][c][slot10]: k0-4 @0-4, k5-8 @6-9 (11520 B)
#define OFF_SBF   11520                     // u32[2304] B fragments
#define OFF_SB    20736                     // u64[10] bias pairs
#define OFF_TILE  20816                     // x tile 22*22*16 f32, linear
#define SMEM_BYTES (OFF_TILE + SH*SW*16*4)  // 51792

typedef unsigned long long u64;

__device__ float g_pre [N_*64*HW];
__device__ float g_stat[2*N_*64];

// ---- packed f32x2 helpers ----
__device__ __forceinline__ u64 pack2(float lo, float hi) {
    u64 r; asm("mov.b64 %0,{%1,%2};" : "=l"(r) : "f"(lo), "f"(hi)); return r;
}
__device__ __forceinline__ float2 unpack2(u64 v) {
    float2 r; asm("mov.b64 {%0,%1},%2;" : "=f"(r.x), "=f"(r.y) : "l"(v)); return r;
}
__device__ __forceinline__ void ffma2(u64 &d, u64 a, u64 b) {
    asm("fma.rn.f32x2 %0,%1,%2,%0;" : "+l"(d) : "l"(a), "l"(b));
}
__device__ __forceinline__ u64 mul2(u64 a, u64 b) {
    u64 r; asm("mul.rn.f32x2 %0,%1,%2;" : "=l"(r) : "l"(a), "l"(b)); return r;
}
__device__ __forceinline__ u64 dup2(float v) { return pack2(v, v); }

// fp32 pair -> hi bf16x2 word + lo residual bf16x2 word
__device__ __forceinline__ void cvt_split(u64 vp, uint32_t &hw, uint32_t &lw) {
    float2 v = unpack2(vp);
    uint32_t h;
    asm("cvt.rn.bf16x2.f32 %0, %1, %2;" : "=r"(h) : "f"(v.y), "f"(v.x));
    const float h0 = __uint_as_float(h << 16);
    const float h1 = __uint_as_float(h & 0xffff0000u);
    const float l0 = v.x - h0, l1 = v.y - h1;
    uint32_t l;
    asm("cvt.rn.bf16x2.f32 %0, %1, %2;" : "=r"(l) : "f"(l1), "f"(l0));
    hw = h; lw = l;
}

__device__ __forceinline__ void bf16split(float w, uint32_t &hi, uint32_t &lo) {
    const uint32_t b = __float_as_uint(w);
    hi = (b + 0x7fffu + ((b >> 16) & 1u)) >> 16;
    const float r = w - __uint_as_float(hi << 16);
    const uint32_t b2 = __float_as_uint(r);
    lo = (b2 + 0x7fffu + ((b2 >> 16) & 1u)) >> 16;
}

// legacy tensor-core path (no sm_103a-gated features)
__device__ __forceinline__ void ldsm4(uint32_t* r, uint32_t addr) {
    asm volatile("ldmatrix.sync.aligned.m8n8.x4.shared.b16 {%0,%1,%2,%3}, [%4];"
        : "=r"(r[0]), "=r"(r[1]), "=r"(r[2]), "=r"(r[3]) : "r"(addr));
}
__device__ __forceinline__ void mma16816(float* d, const uint32_t* a, uint2 b) {
    asm volatile("mma.sync.aligned.m16n8k16.row.col.f32.bf16.bf16.f32 "
        "{%0,%1,%2,%3}, {%4,%5,%6,%7}, {%8,%9}, {%0,%1,%2,%3};"
        : "+f"(d[0]), "+f"(d[1]), "+f"(d[2]), "+f"(d[3])
        : "r"(a[0]), "r"(a[1]), "r"(a[2]), "r"(a[3]), "r"(b.x), "r"(b.y));
}

// Conv k-chunk: taps [KLO, KLO+S) for 2 adjacent pixel rows (fp32 weights)
template<int KLO, int S>
__device__ __forceinline__ void conv_chunk(
    u64 ao_mem[PPT][9], const float* __restrict__ tile,
    const u64* __restrict__ swc, const u64* __restrict__ sb,
    int rloc, int lanex)
{
    u64 ao[PPT][S];
    #pragma unroll
    for (int pix = 0; pix < PPT; pix++)
        #pragma unroll
        for (int kk = 0; kk < S; kk++) ao[pix][kk] = sb[KLO + kk];

    #pragma unroll 1
    for (int j = 0; j < 4; j++) {
        #pragma unroll 1
        for (int cx = 0; cx < 3; cx++) {
            float4 R[4];
            #pragma unroll
            for (int ry = 0; ry < 4; ry++) {
                const int pp = (rloc + HALO - 1 + ry) * SW + (lanex + HALO - 1 + cx);
                R[ry] = *reinterpret_cast<const float4*>(tile + pp * 16 + 4*j);
            }
            #pragma unroll
            for (int posr = 0; posr < 3; posr++) {
                const int pos = posr * 3 + cx;
                #pragma unroll
                for (int q = 0; q < 4; q++) {
                    const u64* wb = swc + (pos * 16 + 4*j + q) * 10;
                    u64 wr[S];
                    if (S == 5) {
                        const ulonglong2 a = *reinterpret_cast<const ulonglong2*>(wb);
                        const ulonglong2 b = *reinterpret_cast<const ulonglong2*>(wb + 2);
                        wr[0] = a.x; wr[1] = a.y; wr[2] = b.x; wr[3] = b.y; wr[4] = wb[4];
                    } else {
                        const ulonglong2 a = *reinterpret_cast<const ulonglong2*>(wb + 6);
                        const ulonglong2 b = *reinterpret_cast<const ulonglong2*>(wb + 8);
                        wr[0] = a.x; wr[1] = a.y; wr[2] = b.x; wr[3] = b.y;
                    }
                    #pragma unroll
                    for (int pix = 0; pix < PPT; pix++) {
                        const float4 X = R[pix + posr];
                        const float xv = (q==0)?X.x:(q==1)?X.y:(q==2)?X.z:X.w;
                        const u64 xd = dup2(xv);
                        #pragma unroll
                        for (int kk = 0; kk < S; kk++) ffma2(ao[pix][kk], wr[kk], xd);
                    }
                }
            }
        }
    }
    #pragma unroll
    for (int pix = 0; pix < PPT; pix++)
        #pragma unroll
        for (int kk = 0; kk < S; kk++) ao_mem[pix][KLO + kk] = ao[pix][kk];
}

__global__ __launch_bounds__(THREADS, 4) void fused_kernel(const float* __restrict__ x,
                                                           const float* __restrict__ w_off,
                                                           const float* __restrict__ b_off,
                                                           const float* __restrict__ w_dc) {
    extern __shared__ __align__(16) char smem_raw[];
    u64*      swc   = reinterpret_cast<u64*>(smem_raw);            // aliased w/ stage
    uint32_t* sbf   = reinterpret_cast<uint32_t*>(smem_raw + OFF_SBF);
    u64*      sb    = reinterpret_cast<u64*>(smem_raw + OFF_SB);
    float*    tile  = reinterpret_cast<float*>(smem_raw + OFF_TILE);

    const int tid = threadIdx.x;
    const int lane = tid & 31, warp = tid >> 5;
    const int bx = blockIdx.x, g = blockIdx.y, n = blockIdx.z;
    const int ty0 = (bx >> 2) * TH, tx0 = (bx & 3) * TW;
    const float* xg = x + ((size_t)(n * 64 + g * 16)) * HW;
    const uint32_t smem_base = (uint32_t)__cvta_generic_to_shared(smem_raw);

    // conv weights (f32x2 pairs): 10 slots/c: k0-4 @0-4, pad @5, k5-8 @6-9
    for (int i = tid; i < SWC_U64; i += THREADS) {
        const int slot = i % 10, c = (i / 10) % 16, pos = i / 160;
        int k = -1;
        if (slot < 5) k = slot;
        else if (slot >= 6) k = slot - 1;
        u64 v = 0ULL;
        if (k >= 0)
            v = pack2(w_off[((g*18 + 2*k)   * 16 + c) * 9 + pos],
                      w_off[((g*18 + 2*k+1) * 16 + c) * 9 + pos]);
        swc[i] = v;
    }
    if (tid < 10)
        sb[tid] = (tid < 9) ? pack2(b_off[g*18 + 2*tid], b_off[g*18 + 2*tid + 1]) : 0ULL;

    // einsum B fragments in m16n8k16 ownership layout: [k][term][nt][lane][reg]
    for (int i = tid; i < 2304; i += THREADS) {
        const int reg  = i & 1;
        const int ln   = (i >> 1) & 31;
        const int nt   = (i >> 6) & 1;
        const int term = (i >> 7) & 1;
        const int k    = i >> 8;
        const int gidp = ln >> 2, tigp = ln & 3;
        const int o  = nt * 8 + gidp;
        const int c0 = tigp * 2 + reg * 8;
        uint32_t h0, l0, h1, l1;
        bf16split(w_dc[((g*16 + o) * 16 + c0    ) * 9 + k], h0, l0);
        bf16split(w_dc[((g*16 + o) * 16 + c0 + 1) * 9 + k], h1, l1);
        sbf[i] = (term == 0) ? (h0 | (h1 << 16)) : (l0 | (l1 << 16));
    }

    // x tile, linear (zero halo = conv boundary skip)
    for (int sp = tid; sp < SH * SW; sp += THREADS) {
        const int gy = ty0 - HALO + sp / SW;
        const int gx = tx0 - HALO + sp % SW;
        const bool in = ((unsigned)gy < 64u) && ((unsigned)gx < 64u);
        const int gp = gy * 64 + gx;
        #pragma unroll
        for (int c = 0; c < 16; c++)
            tile[sp * 16 + c] = in ? xg[(size_t)c * HW + gp] : 0.f;
    }
    __syncthreads();

    const int y     = tid >> 4;          // 0..7
    const int rloc  = y * PPT;           // 2 adjacent pixel rows
    const int lanex = tid & 15;
    const int yp    = y & 1;

    // ---- Phase A: offset conv in two k-chunks (reads swc) ----
    u64 ao_mem[PPT][9];
    conv_chunk<0, 5>(ao_mem, tile, swc, sb, rloc, lanex);
    conv_chunk<5, 4>(ao_mem, tile, swc, sb, rloc, lanex);

    // All warps done with swc before stage overwrites it
    __syncthreads();

    // ---- Phase B: per tap: sample -> stage (SoA) -> ldmatrix -> mma ----
    float acc[4][2][4];   // [tile][nt][reg]
    #pragma unroll
    for (int t = 0; t < 4; t++)
        #pragma unroll
        for (int nt = 0; nt < 2; nt++)
            #pragma unroll
            for (int r = 0; r < 4; r++) acc[t][nt][r] = 0.f;

    const int oy = ty0 - HALO, ox = tx0 - HALO;
    // SoA stage: per warp two 1024B planes (k-part 0/1), row = px*16B contiguous
    const uint32_t lmbase = smem_base + OFF_STAGE + warp * 2048
                          + ((lane >> 4) & 1) * 1024 + (lane & 15) * 16;
    char* stage_w = smem_raw + OFF_STAGE + warp * 2048;

    #pragma unroll 1
    for (int k = 0; k < 9; k++) {
        const int kdy = k / 3 - 1, kdx = k % 3 - 1;
        const uint2 bh0 = *reinterpret_cast<const uint2*>(sbf + ((k*2+0)*2+0)*64 + lane*2);
        const uint2 bh1 = *reinterpret_cast<const uint2*>(sbf + ((k*2+0)*2+1)*64 + lane*2);
        const uint2 bl0 = *reinterpret_cast<const uint2*>(sbf + ((k*2+1)*2+0)*64 + lane*2);
        const uint2 bl1 = *reinterpret_cast<const uint2*>(sbf + ((k*2+1)*2+1)*64 + lane*2);

        uint32_t low[PPT][8];
        #pragma unroll
        for (int pix = 0; pix < PPT; pix++) {
            const float2 off = unpack2(ao_mem[pix][k]);
            const int hg = ty0 + rloc + pix;
            const int wg = tx0 + lanex;
            const float py = (float)(hg + kdy) + off.x;
            const float px = (float)(wg + kdx) + off.y;
            const float y0f = floorf(py), x0f = floorf(px);
            const float fy = py - y0f, fx = px - x0f;
            const int y0 = (int)y0f, x0 = (int)x0f;
            const bool vy0 = (y0 >= 0)  && (y0 < 64);
            const bool vy1 = (y0 >= -1) && (y0 < 63);
            const bool vx0 = (x0 >= 0)  && (x0 < 64);
            const bool vx1 = (x0 >= -1) && (x0 < 63);
            const u64 w00 = dup2((1.f-fy)*(1.f-fx) * ((vy0&&vx0)?1.f:0.f));
            const u64 w01 = dup2((1.f-fy)*fx       * ((vy0&&vx1)?1.f:0.f));
            const u64 w10 = dup2(fy*(1.f-fx)       * ((vy1&&vx0)?1.f:0.f));
            const u64 w11 = dup2(fy*fx             * ((vy1&&vx1)?1.f:0.f));
            const int yc0 = min(max(y0,0),63), yc1 = min(max(y0+1,0),63);
            const int xc0 = min(max(x0,0),63), xc1 = min(max(x0+1,0),63);
            const int t0y = yc0-oy, t1y = yc1-oy, t0x = xc0-ox, t1x = xc1-ox;
            const bool win = (t0y>=0)&&(t1y<SH)&&(t0x>=0)&&(t1x<SW);
            int p0i, p1i, p2i, p3i;
            if (win) {
                p0i=t0y*SW+t0x; p1i=t0y*SW+t1x; p2i=t1y*SW+t0x; p3i=t1y*SW+t1x;
            } else {
                p0i=yc0*64+xc0; p1i=yc0*64+xc1; p2i=yc1*64+xc0; p3i=yc1*64+xc1;
            }
            uint32_t hiw[8];
            #pragma unroll
            for (int j = 0; j < 4; j++) {
                ulonglong2 A2, B2, C2, D2;
                if (win) {
                    A2 = *reinterpret_cast<const ulonglong2*>(tile + p0i*16 + 4*j);
                    B2 = *reinterpret_cast<const ulonglong2*>(tile + p1i*16 + 4*j);
                    C2 = *reinterpret_cast<const ulonglong2*>(tile + p2i*16 + 4*j);
                    D2 = *reinterpret_cast<const ulonglong2*>(tile + p3i*16 + 4*j);
                } else {
                    const float* xq = xg + (size_t)(4*j) * HW;
                    A2.x = pack2(xq[p0i], xq[HW+p0i]); A2.y = pack2(xq[2*HW+p0i], xq[3*HW+p0i]);
                    B2.x = pack2(xq[p1i], xq[HW+p1i]); B2.y = pack2(xq[2*HW+p1i], xq[3*HW+p1i]);
                    C2.x = pack2(xq[p2i], xq[HW+p2i]); C2.y = pack2(xq[2*HW+p2i], xq[3*HW+p2i]);
                    D2.x = pack2(xq[p3i], xq[HW+p3i]); D2.y = pack2(xq[2*HW+p3i], xq[3*HW+p3i]);
                }
                u64 v01 = mul2(w00, A2.x);
                ffma2(v01, w01, B2.x); ffma2(v01, w10, C2.x); ffma2(v01, w11, D2.x);
                u64 v23 = mul2(w00, A2.y);
                ffma2(v23, w01, B2.y); ffma2(v23, w10, C2.y); ffma2(v23, w11, D2.y);
                cvt_split(v01, hiw[2*j],   low[pix][2*j]);
                cvt_split(v23, hiw[2*j+1], low[pix][2*j+1]);
            }
            const int pxidx = (yp * 2 + pix) * 16 + lanex;
            *reinterpret_cast<uint4*>(stage_w + pxidx * 16) =
                make_uint4(hiw[0], hiw[1], hiw[2], hiw[3]);
            *reinterpret_cast<uint4*>(stage_w + 1024 + pxidx * 16) =
                make_uint4(hiw[4], hiw[5], hiw[6], hiw[7]);
        }
        __syncwarp();
        #pragma unroll
        for (int t = 0; t < 4; t++) {
            uint32_t a[4];
            ldsm4(a, lmbase + t * 256);
            mma16816(acc[t][0], a, bh0);
            mma16816(acc[t][1], a, bh1);
            mma16816(acc[t][0], a, bl0);
            mma16816(acc[t][1], a, bl1);
        }
        __syncwarp();
        // stage lo, mma with wh
        #pragma unroll
        for (int pix = 0; pix < PPT; pix++) {
            const int pxidx = (yp * 2 + pix) * 16 + lanex;
            *reinterpret_cast<uint4*>(stage_w + pxidx * 16) =
                make_uint4(low[pix][0], low[pix][1], low[pix][2], low[pix][3]);
            *reinterpret_cast<uint4*>(stage_w + 1024 + pxidx * 16) =
                make_uint4(low[pix][4], low[pix][5], low[pix][6], low[pix][7]);
        }
        __syncwarp();
        #pragma unroll
        for (int t = 0; t < 4; t++) {
            uint32_t a[4];
            ldsm4(a, lmbase + t * 256);
            mma16816(acc[t][0], a, bh0);
            mma16816(acc[t][1], a, bh1);
        }
        __syncwarp();
    }

    // ---- writeback: tile t=(typ*2+pixl), row = ty0 + 4*warp + typ*2 + pixl
    const int gid = lane >> 2, tig = lane & 3;
    #pragma unroll
    for (int t = 0; t < 4; t++) {
        const int typ = t >> 1, pixl = t & 1;
        const int row = ty0 + 4 * warp + typ * 2 + pixl;
        #pragma unroll
        for (int nt = 0; nt < 2; nt++) {
            const int o = g * 16 + nt * 8 + 2 * tig;
            float* base = g_pre + (size_t)(n * 64 + o) * HW + row * 64 + tx0;
            base[gid]          = acc[t][nt][0];
            base[HW + gid]     = acc[t][nt][1];
            base[gid + 8]      = acc[t][nt][2];
            base[HW + gid + 8] = acc[t][nt][3];
        }
    }
}

// Reduce g_pre plane -> mean & rsqrt(var) per (n, oc)
__global__ void stats_kernel() {
    __shared__ float sh[8];
    const int i = blockIdx.x;
    const float* p = g_pre + (size_t)i * HW;
    float s = 0.f, q = 0.f;
    for (int t = threadIdx.x; t < HW / 4; t += 128) {
        const float4 v = reinterpret_cast<const float4*>(p)[t];
        s += (v.x + v.y) + (v.z + v.w);
        q += v.x*v.x + v.y*v.y + v.z*v.z + v.w*v.w;
    }
    #pragma unroll
    for (int d = 16; d; d >>= 1) {
        s += __shfl_xor_sync(0xffffffffu, s, d);
        q += __shfl_xor_sync(0xffffffffu, q, d);
    }
    const int w = threadIdx.x >> 5;
    if ((threadIdx.x & 31) == 0) { sh[w] = s; sh[4 + w] = q; }
    __syncthreads();
    if (threadIdx.x == 0) {
        s = sh[0] + sh[1] + sh[2] + sh[3];
        q = sh[4] + sh[5] + sh[6] + sh[7];
        const float mean = s * (1.f / HW);
        const float var  = q * (1.f / HW) - mean * mean;
        g_stat[i]           = mean;
        g_stat[N_*64 + i]   = rsqrtf(var + 1e-5f);
    }
}

// Normalize + exact GELU + transposed store
__global__ void norm_gelu_kernel(float* __restrict__ out) {
    const int oc = blockIdx.y;
    const int n  = blockIdx.z;
    const float mean = g_stat[n*64 + oc];
    const float inv  = g_stat[N_*64 + n*64 + oc];

    const int p4 = blockIdx.x * blockDim.x + threadIdx.x;
    const float4 v = reinterpret_cast<const float4*>(g_pre + ((size_t)(n*64 + oc)) * HW)[p4];
    float4 r;
    { const float a = (v.x-mean)*inv; r.x = 0.5f*a*(1.f+erff(a*0.7071067811865475f)); }
    { const float a = (v.y-mean)*inv; r.y = 0.5f*a*(1.f+erff(a*0.7071067811865475f)); }
    { const float a = (v.z-mean)*inv; r.z = 0.5f*a*(1.f+erff(a*0.7071067811865475f)); }
    { const float a = (v.w-mean)*inv; r.w = 0.5f*a*(1.f+erff(a*0.7071067811865475f)); }

    const int b = n >> 3, d = n & 7;
    reinterpret_cast<float4*>(out + ((size_t)((b*64 + oc)*8 + d)) * HW)[p4] = r;
}

extern "C" void kernel_launch(void* const* d_in, const int* in_sizes, int n_in,
                              void* d_out, int out_size) {
    const float* x     = (const float*)d_in[0];
    const float* w_off = (const float*)d_in[1];
    const float* b_off = (const float*)d_in[2];
    const float* w_dc  = (const float*)d_in[3];
    // d_in[4] = b_dc: cancels exactly under per-channel mean subtraction.
    float* out = (float*)d_out;

    cudaFuncSetAttribute(fused_kernel,
                         cudaFuncAttributeMaxDynamicSharedMemorySize, SMEM_BYTES);

    fused_kernel<<<dim3(16, G_, N_), THREADS, SMEM_BYTES>>>(x, w_off, b_off, w_dc);
    stats_kernel<<<N_ * 64, 128>>>();
    norm_gelu_kernel<<<dim3(HW / 1024, 64, N_), 256>>>(out);
}

// round 17
// speedup vs baseline: 1.7545x; 1.7545x over previous
#include <cuda_runtime.h>
#include <math.h>
#include <stdint.h>

#define G_   4
#define HW   4096
#define N_   32
#define TH   32
#define TW   16
#define HALO 3
#define SH   38
#define SW   22
#define THREADS 128
#define PPT  4

// smem layout (bytes). Stage (SoA, conflict-free) aliases conv-weight table.
#define OFF_STAGE 0
#define SWC_U64   1440                      // 11520 B (aliased region max)
#define OFF_SBF   11520                     // u32[2304] B fragments
#define OFF_SB    20736                     // u64[10] bias pairs
#define OFF_TILE  20816                     // x tile 38*22*16 floats, quad-swizzled
#define SMEM_BYTES (OFF_TILE + SH*SW*16*4)  // 74320

typedef unsigned long long u64;

__device__ float g_pre [N_*64*HW];
__device__ float g_part[N_*4*8*32];         // [n][g][bx][sum16|sq16]
__device__ float g_stat[2*N_*64];

// ---- packed f32x2 helpers ----
__device__ __forceinline__ u64 pack2(float lo, float hi) {
    u64 r; asm("mov.b64 %0,{%1,%2};" : "=l"(r) : "f"(lo), "f"(hi)); return r;
}
__device__ __forceinline__ float2 unpack2(u64 v) {
    float2 r; asm("mov.b64 {%0,%1},%2;" : "=f"(r.x), "=f"(r.y) : "l"(v)); return r;
}
__device__ __forceinline__ void ffma2(u64 &d, u64 a, u64 b) {
    asm("fma.rn.f32x2 %0,%1,%2,%0;" : "+l"(d) : "l"(a), "l"(b));
}
__device__ __forceinline__ u64 mul2(u64 a, u64 b) {
    u64 r; asm("mul.rn.f32x2 %0,%1,%2;" : "=l"(r) : "l"(a), "l"(b)); return r;
}
__device__ __forceinline__ u64 dup2(float v) { return pack2(v, v); }

// fp32 pair -> hi bf16x2 word + lo residual bf16x2 word
__device__ __forceinline__ void cvt_split(u64 vp, uint32_t &hw, uint32_t &lw) {
    float2 v = unpack2(vp);
    uint32_t h;
    asm("cvt.rn.bf16x2.f32 %0, %1, %2;" : "=r"(h) : "f"(v.y), "f"(v.x));
    const float h0 = __uint_as_float(h << 16);
    const float h1 = __uint_as_float(h & 0xffff0000u);
    const float l0 = v.x - h0, l1 = v.y - h1;
    uint32_t l;
    asm("cvt.rn.bf16x2.f32 %0, %1, %2;" : "=r"(l) : "f"(l1), "f"(l0));
    hw = h; lw = l;
}

__device__ __forceinline__ void bf16split(float w, uint32_t &hi, uint32_t &lo) {
    const uint32_t b = __float_as_uint(w);
    hi = (b + 0x7fffu + ((b >> 16) & 1u)) >> 16;
    const float r = w - __uint_as_float(hi << 16);
    const uint32_t b2 = __float_as_uint(r);
    lo = (b2 + 0x7fffu + ((b2 >> 16) & 1u)) >> 16;
}

// legacy tensor-core path (no sm_103a-gated features)
__device__ __forceinline__ void ldsm4(uint32_t* r, uint32_t addr) {
    asm volatile("ldmatrix.sync.aligned.m8n8.x4.shared.b16 {%0,%1,%2,%3}, [%4];"
        : "=r"(r[0]), "=r"(r[1]), "=r"(r[2]), "=r"(r[3]) : "r"(addr));
}
__device__ __forceinline__ void mma16816(float* d, const uint32_t* a, uint2 b) {
    asm volatile("mma.sync.aligned.m16n8k16.row.col.f32.bf16.bf16.f32 "
        "{%0,%1,%2,%3}, {%4,%5,%6,%7}, {%8,%9}, {%0,%1,%2,%3};"
        : "+f"(d[0]), "+f"(d[1]), "+f"(d[2]), "+f"(d[3])
        : "r"(a[0]), "r"(a[1]), "r"(a[2]), "r"(a[3]), "r"(b.x), "r"(b.y));
}

// quad-swizzled tile addressing: pixel p, channel-quad j at
//   tile[p*16 + ((j + (p>>1)) & 3)*4]  -> conflict-free for consecutive pixels
__device__ __forceinline__ const float4* tquad(const float* tile, int p, int j) {
    return reinterpret_cast<const float4*>(tile + p * 16 + (((j + (p >> 1)) & 3) << 2));
}

// Conv k-chunk: taps [KLO, KLO+S) for 4 adjacent pixel rows, results -> ao_mem
template<int KLO, int S>
__device__ __forceinline__ void conv_chunk(
    u64 ao_mem[PPT][9], const float* __restrict__ tile,
    const u64* __restrict__ swc, const u64* __restrict__ sb,
    int rloc, int lanex)
{
    u64 ao[PPT][S];
    #pragma unroll
    for (int pix = 0; pix < PPT; pix++)
        #pragma unroll
        for (int kk = 0; kk < S; kk++) ao[pix][kk] = sb[KLO + kk];

    #pragma unroll 1
    for (int j = 0; j < 4; j++) {
        #pragma unroll 1
        for (int cx = 0; cx < 3; cx++) {
            float4 R[6];
            #pragma unroll
            for (int ry = 0; ry < 6; ry++) {
                const int pp = (rloc + HALO - 1 + ry) * SW + (lanex + HALO - 1 + cx);
                R[ry] = *tquad(tile, pp, j);
            }
            #pragma unroll
            for (int posr = 0; posr < 3; posr++) {
                const int pos = posr * 3 + cx;
                #pragma unroll
                for (int q = 0; q < 4; q++) {
                    const u64* wb = swc + (pos * 16 + 4*j + q) * 10;
                    u64 wr[S];
                    if (S == 5) {
                        const ulonglong2 a = *reinterpret_cast<const ulonglong2*>(wb);
                        const ulonglong2 b = *reinterpret_cast<const ulonglong2*>(wb + 2);
                        wr[0] = a.x; wr[1] = a.y; wr[2] = b.x; wr[3] = b.y; wr[4] = wb[4];
                    } else {
                        const ulonglong2 a = *reinterpret_cast<const ulonglong2*>(wb + 6);
                        const ulonglong2 b = *reinterpret_cast<const ulonglong2*>(wb + 8);
                        wr[0] = a.x; wr[1] = a.y; wr[2] = b.x; wr[3] = b.y;
                    }
                    #pragma unroll
                    for (int pix = 0; pix < PPT; pix++) {
                        const float4 X = R[pix + posr];
                        const float xv = (q==0)?X.x:(q==1)?X.y:(q==2)?X.z:X.w;
                        const u64 xd = dup2(xv);
                        #pragma unroll
                        for (int kk = 0; kk < S; kk++) ffma2(ao[pix][kk], wr[kk], xd);
                    }
                }
            }
        }
    }
    #pragma unroll
    for (int pix = 0; pix < PPT; pix++)
        #pragma unroll
        for (int kk = 0; kk < S; kk++) ao_mem[pix][KLO + kk] = ao[pix][kk];
}

__global__ __launch_bounds__(THREADS) void fused_kernel(const float* __restrict__ x,
                                                        const float* __restrict__ w_off,
                                                        const float* __restrict__ b_off,
                                                        const float* __restrict__ w_dc) {
    extern __shared__ __align__(16) char smem_raw[];
    u64*      swc   = reinterpret_cast<u64*>(smem_raw);            // aliased w/ stage
    uint32_t* sbf   = reinterpret_cast<uint32_t*>(smem_raw + OFF_SBF);
    u64*      sb    = reinterpret_cast<u64*>(smem_raw + OFF_SB);
    float*    tile  = reinterpret_cast<float*>(smem_raw + OFF_TILE);
    __shared__ float s_red[4][32];

    const int tid = threadIdx.x;
    const int lane = tid & 31, warp = tid >> 5;
    const int bx = blockIdx.x, g = blockIdx.y, n = blockIdx.z;
    const int ty0 = (bx >> 2) * TH, tx0 = (bx & 3) * TW;
    const float* xg = x + ((size_t)(n * 64 + g * 16)) * HW;
    const uint32_t smem_base = (uint32_t)__cvta_generic_to_shared(smem_raw);

    // conv weights (f32x2 pairs): 10 slots/c: k0-4 @0-4, pad @5, k5-8 @6-9
    for (int i = tid; i < SWC_U64; i += THREADS) {
        const int slot = i % 10, c = (i / 10) % 16, pos = i / 160;
        int k = -1;
        if (slot < 5) k = slot;
        else if (slot >= 6) k = slot - 1;
        u64 v = 0ULL;
        if (k >= 0)
            v = pack2(w_off[((g*18 + 2*k)   * 16 + c) * 9 + pos],
                      w_off[((g*18 + 2*k+1) * 16 + c) * 9 + pos]);
        swc[i] = v;
    }
    if (tid < 10)
        sb[tid] = (tid < 9) ? pack2(b_off[g*18 + 2*tid], b_off[g*18 + 2*tid + 1]) : 0ULL;

    // einsum B fragments in m16n8k16 ownership layout: [k][term][nt][lane][reg]
    for (int i = tid; i < 2304; i += THREADS) {
        const int reg  = i & 1;
        const int ln   = (i >> 1) & 31;
        const int nt   = (i >> 6) & 1;
        const int term = (i >> 7) & 1;
        const int k    = i >> 8;
        const int gidp = ln >> 2, tigp = ln & 3;
        const int o  = nt * 8 + gidp;
        const int c0 = tigp * 2 + reg * 8;
        uint32_t h0, l0, h1, l1;
        bf16split(w_dc[((g*16 + o) * 16 + c0    ) * 9 + k], h0, l0);
        bf16split(w_dc[((g*16 + o) * 16 + c0 + 1) * 9 + k], h1, l1);
        sbf[i] = (term == 0) ? (h0 | (h1 << 16)) : (l0 | (l1 << 16));
    }

    // x tile, quad-swizzled (zero halo = conv boundary skip)
    for (int sp = tid; sp < SH * SW; sp += THREADS) {
        const int gy = ty0 - HALO + sp / SW;
        const int gx = tx0 - HALO + sp % SW;
        const bool in = ((unsigned)gy < 64u) && ((unsigned)gx < 64u);
        const int gp = gy * 64 + gx;
        const int swb = (sp >> 1) & 3;
        #pragma unroll
        for (int c = 0; c < 16; c++) {
            const int slot = ((((c >> 2) + swb) & 3) << 2) | (c & 3);
            tile[sp * 16 + slot] = in ? xg[(size_t)c * HW + gp] : 0.f;
        }
    }
    __syncthreads();

    const int y     = tid >> 4;          // 0..7
    const int rloc  = y * PPT;           // 4 adjacent pixel rows
    const int lanex = tid & 15;
    const int yp    = y & 1;

    // ---- Phase A: offset conv in two k-chunks (reads swc) ----
    u64 ao_mem[PPT][9];
    conv_chunk<0, 5>(ao_mem, tile, swc, sb, rloc, lanex);
    conv_chunk<5, 4>(ao_mem, tile, swc, sb, rloc, lanex);

    __syncthreads();   // all warps done with swc before stage overwrites it

    // ---- Phase B: per tap, two pixel-pair passes: sample -> stage -> mma ----
    float acc[2][4][2][4];   // [pass][tile][nt][reg]
    #pragma unroll
    for (int p = 0; p < 2; p++)
        #pragma unroll
        for (int t = 0; t < 4; t++)
            #pragma unroll
            for (int nt = 0; nt < 2; nt++)
                #pragma unroll
                for (int r = 0; r < 4; r++) acc[p][t][nt][r] = 0.f;

    const int oy = ty0 - HALO, ox = tx0 - HALO;
    const uint32_t lmbase = smem_base + OFF_STAGE + warp * 2048
                          + ((lane >> 4) & 1) * 1024 + (lane & 15) * 16;
    char* stage_w = smem_raw + OFF_STAGE + warp * 2048;

    #pragma unroll 1
    for (int k = 0; k < 9; k++) {
        const int kdy = k / 3 - 1, kdx = k % 3 - 1;
        const uint2 bh0 = *reinterpret_cast<const uint2*>(sbf + ((k*2+0)*2+0)*64 + lane*2);
        const uint2 bh1 = *reinterpret_cast<const uint2*>(sbf + ((k*2+0)*2+1)*64 + lane*2);
        const uint2 bl0 = *reinterpret_cast<const uint2*>(sbf + ((k*2+1)*2+0)*64 + lane*2);
        const uint2 bl1 = *reinterpret_cast<const uint2*>(sbf + ((k*2+1)*2+1)*64 + lane*2);

        #pragma unroll
        for (int p = 0; p < 2; p++) {
            uint32_t low[2][8];
            #pragma unroll
            for (int pixl = 0; pixl < 2; pixl++) {
                const int pix = 2*p + pixl;
                const float2 off = unpack2(ao_mem[pix][k]);
                const int hg = ty0 + rloc + pix;
                const int wg = tx0 + lanex;
                const float py = (float)(hg + kdy) + off.x;
                const float px = (float)(wg + kdx) + off.y;
                const float y0f = floorf(py), x0f = floorf(px);
                const float fy = py - y0f, fx = px - x0f;
                const int y0 = (int)y0f, x0 = (int)x0f;
                const bool vy0 = (y0 >= 0)  && (y0 < 64);
                const bool vy1 = (y0 >= -1) && (y0 < 63);
                const bool vx0 = (x0 >= 0)  && (x0 < 64);
                const bool vx1 = (x0 >= -1) && (x0 < 63);
                const u64 w00 = dup2((1.f-fy)*(1.f-fx) * ((vy0&&vx0)?1.f:0.f));
                const u64 w01 = dup2((1.f-fy)*fx       * ((vy0&&vx1)?1.f:0.f));
                const u64 w10 = dup2(fy*(1.f-fx)       * ((vy1&&vx0)?1.f:0.f));
                const u64 w11 = dup2(fy*fx             * ((vy1&&vx1)?1.f:0.f));
                const int yc0 = min(max(y0,0),63), yc1 = min(max(y0+1,0),63);
                const int xc0 = min(max(x0,0),63), xc1 = min(max(x0+1,0),63);
                const int t0y = yc0-oy, t1y = yc1-oy, t0x = xc0-ox, t1x = xc1-ox;
                const bool win = (t0y>=0)&&(t1y<SH)&&(t0x>=0)&&(t1x<SW);
                int p0i, p1i, p2i, p3i;
                if (win) {
                    p0i=t0y*SW+t0x; p1i=t0y*SW+t1x; p2i=t1y*SW+t0x; p3i=t1y*SW+t1x;
                } else {
                    p0i=yc0*64+xc0; p1i=yc0*64+xc1; p2i=yc1*64+xc0; p3i=yc1*64+xc1;
                }
                uint32_t hiw[8];
                #pragma unroll
                for (int j = 0; j < 4; j++) {
                    ulonglong2 A2, B2, C2, D2;
                    if (win) {
                        A2 = *reinterpret_cast<const ulonglong2*>(tquad(tile, p0i, j));
                        B2 = *reinterpret_cast<const ulonglong2*>(tquad(tile, p1i, j));
                        C2 = *reinterpret_cast<const ulonglong2*>(tquad(tile, p2i, j));
                        D2 = *reinterpret_cast<const ulonglong2*>(tquad(tile, p3i, j));
                    } else {
                        const float* xq = xg + (size_t)(4*j) * HW;
                        A2.x = pack2(xq[p0i], xq[HW+p0i]); A2.y = pack2(xq[2*HW+p0i], xq[3*HW+p0i]);
                        B2.x = pack2(xq[p1i], xq[HW+p1i]); B2.y = pack2(xq[2*HW+p1i], xq[3*HW+p1i]);
                        C2.x = pack2(xq[p2i], xq[HW+p2i]); C2.y = pack2(xq[2*HW+p2i], xq[3*HW+p2i]);
                        D2.x = pack2(xq[p3i], xq[HW+p3i]); D2.y = pack2(xq[2*HW+p3i], xq[3*HW+p3i]);
                    }
                    u64 v01 = mul2(w00, A2.x);
                    ffma2(v01, w01, B2.x); ffma2(v01, w10, C2.x); ffma2(v01, w11, D2.x);
                    u64 v23 = mul2(w00, A2.y);
                    ffma2(v23, w01, B2.y); ffma2(v23, w10, C2.y); ffma2(v23, w11, D2.y);
                    cvt_split(v01, hiw[2*j],   low[pixl][2*j]);
                    cvt_split(v23, hiw[2*j+1], low[pixl][2*j+1]);
                }
                const int pxidx = (yp * 2 + pixl) * 16 + lanex;
                *reinterpret_cast<uint4*>(stage_w + pxidx * 16) =
                    make_uint4(hiw[0], hiw[1], hiw[2], hiw[3]);
                *reinterpret_cast<uint4*>(stage_w + 1024 + pxidx * 16) =
                    make_uint4(hiw[4], hiw[5], hiw[6], hiw[7]);
            }
            __syncwarp();
            #pragma unroll
            for (int t = 0; t < 4; t++) {
                uint32_t a[4];
                ldsm4(a, lmbase + t * 256);
                mma16816(acc[p][t][0], a, bh0);
                mma16816(acc[p][t][1], a, bh1);
                mma16816(acc[p][t][0], a, bl0);
                mma16816(acc[p][t][1], a, bl1);
            }
            __syncwarp();
            #pragma unroll
            for (int pixl = 0; pixl < 2; pixl++) {
                const int pxidx = (yp * 2 + pixl) * 16 + lanex;
                *reinterpret_cast<uint4*>(stage_w + pxidx * 16) =
                    make_uint4(low[pixl][0], low[pixl][1], low[pixl][2], low[pixl][3]);
                *reinterpret_cast<uint4*>(stage_w + 1024 + pxidx * 16) =
                    make_uint4(low[pixl][4], low[pixl][5], low[pixl][6], low[pixl][7]);
            }
            __syncwarp();
            #pragma unroll
            for (int t = 0; t < 4; t++) {
                uint32_t a[4];
                ldsm4(a, lmbase + t * 256);
                mma16816(acc[p][t][0], a, bh0);
                mma16816(acc[p][t][1], a, bh1);
            }
            __syncwarp();
        }
    }

    // ---- writeback + in-register stats ----
    // fragment layout: reg 0 -> (row gid,   ch 2*tig), reg 1 -> (gid,   2*tig+1),
    //                  reg 2 -> (row gid+8, ch 2*tig), reg 3 -> (gid+8, 2*tig+1)
    const int gid = lane >> 2, tig = lane & 3;
    float sv[2][2], sq[2][2];   // [nt][parity]
    #pragma unroll
    for (int nt = 0; nt < 2; nt++)
        #pragma unroll
        for (int pr = 0; pr < 2; pr++) { sv[nt][pr] = 0.f; sq[nt][pr] = 0.f; }

    #pragma unroll
    for (int p = 0; p < 2; p++) {
        #pragma unroll
        for (int t = 0; t < 4; t++) {
            const int typ = t >> 1, pixl = t & 1;
            const int row = ty0 + (2 * warp + typ) * 4 + 2 * p + pixl;
            #pragma unroll
            for (int nt = 0; nt < 2; nt++) {
                const int o = g * 16 + nt * 8 + 2 * tig;
                float* base = g_pre + (size_t)(n * 64 + o) * HW + row * 64 + tx0;
                base[gid]          = acc[p][t][nt][0];
                base[HW + gid]     = acc[p][t][nt][1];
                base[gid + 8]      = acc[p][t][nt][2];
                base[HW + gid + 8] = acc[p][t][nt][3];
                #pragma unroll
                for (int r = 0; r < 4; r++) {
                    const float v = acc[p][t][nt][r];
                    sv[nt][r & 1] += v;
                    sq[nt][r & 1] += v * v;
                }
            }
        }
    }
    // reduce across lanes with same tig (gid 0..7): xor distances 4,8,16
    #pragma unroll
    for (int d = 4; d <= 16; d <<= 1) {
        #pragma unroll
        for (int nt = 0; nt < 2; nt++)
            #pragma unroll
            for (int pr = 0; pr < 2; pr++) {
                sv[nt][pr] += __shfl_xor_sync(0xffffffffu, sv[nt][pr], d);
                sq[nt][pr] += __shfl_xor_sync(0xffffffffu, sq[nt][pr], d);
            }
    }
    if (gid == 0) {   // lane == tig
        #pragma unroll
        for (int nt = 0; nt < 2; nt++)
            #pragma unroll
            for (int pr = 0; pr < 2; pr++) {
                const int idx = nt * 8 + 2 * tig + pr;
                s_red[warp][idx]      = sv[nt][pr];
                s_red[warp][16 + idx] = sq[nt][pr];
            }
    }
    __syncthreads();
    if (tid < 32) {
        const float v = s_red[0][tid] + s_red[1][tid] + s_red[2][tid] + s_red[3][tid];
        g_part[(((n * 4 + g) * 8) + bx) * 32 + tid] = v;
    }
}

// Reduce 8 block-partials -> mean & rsqrt(var) per (n, oc)
__global__ void stats_kernel() {
    const int i = blockIdx.x * blockDim.x + threadIdx.x;
    if (i >= N_ * 64) return;
    const int n = i >> 6, oc = i & 63;
    const int g = oc >> 4, o = oc & 15;
    float s = 0.f, q = 0.f;
    #pragma unroll
    for (int b = 0; b < 8; b++) {
        const float* pp = g_part + ((n * 4 + g) * 8 + b) * 32;
        s += pp[o]; q += pp[16 + o];
    }
    const float mean = s * (1.f / HW);
    const float var  = q * (1.f / HW) - mean * mean;
    g_stat[i]         = mean;
    g_stat[N_*64 + i] = rsqrtf(var + 1e-5f);
}

// Normalize + exact GELU + transposed store (2x float4 per thread)
__global__ void norm_gelu_kernel(float* __restrict__ out) {
    const int oc = blockIdx.y;
    const int n  = blockIdx.z;
    const float mean = g_stat[n*64 + oc];
    const float inv  = g_stat[N_*64 + n*64 + oc];

    const float4* src = reinterpret_cast<const float4*>(g_pre + ((size_t)(n*64 + oc)) * HW);
    float4* dst;
    {
        const int b = n >> 3, d = n & 7;
        dst = reinterpret_cast<float4*>(out + ((size_t)((b*64 + oc)*8 + d)) * HW);
    }
    const int base = blockIdx.x * 512 + threadIdx.x;
    #pragma unroll
    for (int h = 0; h < 2; h++) {
        const int p4 = base + h * 256;
        const float4 v = src[p4];
        float4 r;
        { const float a = (v.x-mean)*inv; r.x = 0.5f*a*(1.f+erff(a*0.7071067811865475f)); }
        { const float a = (v.y-mean)*inv; r.y = 0.5f*a*(1.f+erff(a*0.7071067811865475f)); }
        { const float a = (v.z-mean)*inv; r.z = 0.5f*a*(1.f+erff(a*0.7071067811865475f)); }
        { const float a = (v.w-mean)*inv; r.w = 0.5f*a*(1.f+erff(a*0.7071067811865475f)); }
        dst[p4] = r;
    }
}

extern "C" void kernel_launch(void* const* d_in, const int* in_sizes, int n_in,
                              void* d_out, int out_size) {
    const float* x     = (const float*)d_in[0];
    const float* w_off = (const float*)d_in[1];
    const float* b_off = (const float*)d_in[2];
    const float* w_dc  = (const float*)d_in[3];
    // d_in[4] = b_dc: cancels exactly under per-channel mean subtraction.
    float* out = (float*)d_out;

    cudaFuncSetAttribute(fused_kernel,
                         cudaFuncAttributeMaxDynamicSharedMemorySize, SMEM_BYTES);

    fused_kernel<<<dim3(8, G_, N_), THREADS, SMEM_BYTES>>>(x, w_off, b_off, w_dc);
    stats_kernel<<<2, 1024>>>();
    norm_gelu_kernel<<<dim3(HW / 2048, 64, N_), 256>>>(out);
}